// round 7
// baseline (speedup 1.0000x reference)
#include <cuda_runtime.h>
#include <math.h>
#include <stdint.h>

#define BATCH   8
#define NTOK    1024
#define DIMSZ   768
#define NHEADS  8
#define HDIM    96
#define NEXP    24
#define TOK     (BATCH*NTOK)        /* 8192  */
#define ROWS    (TOK*NHEADS)        /* 65536 */
#define ATTSCALE 0.10206207261596577f  /* 96^-0.5 */

/* ---------------- scratch (static device memory; no allocations) -------- */
__device__ float g_k[TOK*HDIM];
__device__ float g_v[TOK*HDIM];
__device__ float g_q[(size_t)ROWS*HDIM];
__device__ float g_o[(size_t)ROWS*HDIM];
__device__ float g_contrib[(size_t)ROWS*DIMSZ];   /* 192 MB */
__device__ int   g_topi[ROWS];
__device__ float g_gates[ROWS];
__device__ int   g_perm[ROWS];
__device__ float g_me[NEXP];
__device__ int   g_counts[NEXP];
__device__ int   g_cursor[NEXP];
__device__ int   g_offsets[NEXP+1];
__device__ float g_zsum;
__device__ int   g_t4e[1100], g_t4row[1100], g_nt4;
__device__ int   g_t6e[2200], g_t6row[2200], g_nt6;

/* ---------------- zero counters ---------------------------------------- */
__global__ void zero_kernel() {
    int i = threadIdx.x;
    if (i < NEXP) { g_me[i] = 0.f; g_counts[i] = 0; g_cursor[i] = 0; }
    if (i == 63) g_zsum = 0.f;
}

/* ---------------- gating: logits, softmax, top-8, aux partials ---------- */
__global__ void gate_kernel(const float* __restrict__ x,
                            const float* __restrict__ Wg,
                            const int*   __restrict__ taskp) {
    int t = blockIdx.x;               /* token id 0..8191 */
    int tid = threadIdx.x;            /* 192 threads */
    __shared__ float xs[DIMSZ];
    __shared__ float lred[6][NEXP];
    __shared__ float logits[NEXP];
    __shared__ float probs[NEXP];

    for (int i = tid; i < DIMSZ; i += 192) xs[i] = x[(size_t)t*DIMSZ + i];
    __syncthreads();

    int task = *taskp;
    const float* W = Wg + (size_t)task * DIMSZ * NEXP;

    float acc[NEXP];
#pragma unroll
    for (int e = 0; e < NEXP; e++) acc[e] = 0.f;
    for (int d = tid; d < DIMSZ; d += 192) {
        float xv = xs[d];
        const float* row = W + (size_t)d * NEXP;
#pragma unroll
        for (int e = 0; e < NEXP; e++) acc[e] += xv * row[e];
    }
#pragma unroll
    for (int off = 16; off > 0; off >>= 1)
#pragma unroll
        for (int e = 0; e < NEXP; e++)
            acc[e] += __shfl_xor_sync(0xffffffffu, acc[e], off);
    int warp = tid >> 5, lane = tid & 31;
    if (lane == 0)
#pragma unroll
        for (int e = 0; e < NEXP; e++) lred[warp][e] = acc[e];
    __syncthreads();
    if (tid < NEXP) {
        float s = 0.f;
#pragma unroll
        for (int w = 0; w < 6; w++) s += lred[w][tid];
        logits[tid] = s;
    }
    __syncthreads();

    if (tid == 0) {
        float mx = -1e30f;
        for (int e = 0; e < NEXP; e++) mx = fmaxf(mx, logits[e]);
        float se = 0.f;
        for (int e = 0; e < NEXP; e++) se += expf(logits[e] - mx);
        float lse = mx + logf(se);
        atomicAdd(&g_zsum, lse * lse);
        float inv = 1.f / se;
        for (int e = 0; e < NEXP; e++) probs[e] = expf(logits[e] - mx) * inv;
        /* top-8, stable (lowest index wins ties) */
        bool used[NEXP];
        for (int e = 0; e < NEXP; e++) used[e] = false;
        float gsum = 0.f; int idx[NHEADS]; float gv[NHEADS];
        for (int h = 0; h < NHEADS; h++) {
            float best = -1.f; int bi = 0;
            for (int e = 0; e < NEXP; e++)
                if (!used[e] && probs[e] > best) { best = probs[e]; bi = e; }
            used[bi] = true; idx[h] = bi; gv[h] = best; gsum += best;
        }
        float dn = 1.f / (gsum + 1e-6f);
        for (int h = 0; h < NHEADS; h++) {
            g_topi[t*NHEADS + h]  = idx[h];
            g_gates[t*NHEADS + h] = gv[h] * dn;
            atomicAdd(&g_counts[idx[h]], 1);
        }
    }
    __syncthreads();
    if (tid < NEXP) atomicAdd(&g_me[tid], probs[tid]);
}

/* ---------------- offsets + tile maps (single thread) ------------------- */
__global__ void scan_kernel() {
    int off = 0;
    for (int e = 0; e < NEXP; e++) { g_offsets[e] = off; off += g_counts[e]; }
    g_offsets[NEXP] = off;
    int n4 = 0, n6 = 0;
    for (int e = 0; e < NEXP; e++) {
        int r = g_counts[e];
        for (int i = 0; i < r; i += 64) { g_t4e[n4] = e; g_t4row[n4] = i; n4++; }
        for (int i = 0; i < r; i += 32) { g_t6e[n6] = e; g_t6row[n6] = i; n6++; }
    }
    g_nt4 = n4; g_nt6 = n6;
}

/* ---------------- scatter rows into per-expert lists -------------------- */
__global__ void scatter_kernel() {
    int i = blockIdx.x * 256 + threadIdx.x;
    if (i >= ROWS) return;
    int e = g_topi[i];
    int pos = g_offsets[e] + atomicAdd(&g_cursor[e], 1);
    g_perm[pos] = i;
}

/* ---------------- kv = x @ Wkv + b_kv ----------------------------------- */
__global__ void __launch_bounds__(256) kv_kernel(
                          const float* __restrict__ x,
                          const float* __restrict__ Wkv,
                          const float* __restrict__ bkv) {
    int bm = blockIdx.x * 64, bn = blockIdx.y * 64;
    __shared__ float As[16][65];
    __shared__ float Bs[16][64];
    int tid = threadIdx.x;
    int tx = tid & 15, ty = tid >> 4;
    float acc[4][4];
#pragma unroll
    for (int i = 0; i < 4; i++)
#pragma unroll
        for (int j = 0; j < 4; j++) acc[i][j] = 0.f;
    int lr = tid >> 2, lc4 = (tid & 3) * 4;
    int br = tid >> 4, bc4 = (tid & 15) * 4;
    for (int k0 = 0; k0 < DIMSZ; k0 += 16) {
        float4 av = *(const float4*)(x + (size_t)(bm + lr) * DIMSZ + k0 + lc4);
        As[lc4+0][lr] = av.x; As[lc4+1][lr] = av.y;
        As[lc4+2][lr] = av.z; As[lc4+3][lr] = av.w;
        *(float4*)&Bs[br][bc4] =
            *(const float4*)(Wkv + (size_t)(k0 + br) * 192 + bn + bc4);
        __syncthreads();
#pragma unroll
        for (int kk = 0; kk < 16; kk++) {
            float a[4];
#pragma unroll
            for (int i = 0; i < 4; i++) a[i] = As[kk][ty*4 + i];
            float4 b = *(float4*)&Bs[kk][tx*4];
#pragma unroll
            for (int i = 0; i < 4; i++) {
                acc[i][0] += a[i]*b.x; acc[i][1] += a[i]*b.y;
                acc[i][2] += a[i]*b.z; acc[i][3] += a[i]*b.w;
            }
        }
        __syncthreads();
    }
#pragma unroll
    for (int i = 0; i < 4; i++) {
        int t = bm + ty*4 + i;
#pragma unroll
        for (int j = 0; j < 4; j++) {
            int col = bn + tx*4 + j;
            float val = acc[i][j] + bkv[col];
            if (col < HDIM) g_k[(size_t)t*HDIM + col] = val;
            else            g_v[(size_t)t*HDIM + col - HDIM] = val;
        }
    }
}

/* ---------------- MoE map: q rows per expert (gathered GEMM) ------------ */
__global__ void __launch_bounds__(256) map_kernel(
                           const float* __restrict__ x,
                           const float* __restrict__ W1) {
    if ((int)blockIdx.x >= g_nt4) return;
    int e = g_t4e[blockIdx.x], row0 = g_t4row[blockIdx.x];
    int off = g_offsets[e], rows = g_offsets[e+1] - off;
    __shared__ float As[32][68];
    __shared__ float Bs[32][96];
    __shared__ int   pidx[64];
    int tid = threadIdx.x;
    if (tid < 64) {
        int r = row0 + tid;
        pidx[tid] = (r < rows) ? g_perm[off + r] : -1;
    }
    __syncthreads();
    int tx = tid & 15, ty = tid >> 4;
    float acc[4][6];
#pragma unroll
    for (int i = 0; i < 4; i++)
#pragma unroll
        for (int j = 0; j < 6; j++) acc[i][j] = 0.f;
    int am = tid >> 2, aseg = tid & 3;
    int bk = tid >> 3, bseg = tid & 7;
    const float* Wb = W1 + (size_t)e * DIMSZ * HDIM;
    int p_am = pidx[am];
    const float* xrow = (p_am >= 0) ? x + (size_t)(p_am >> 3) * DIMSZ : x;
    for (int k0 = 0; k0 < DIMSZ; k0 += 32) {
#pragma unroll
        for (int u = 0; u < 2; u++) {
            int kk = aseg*4 + u*16;
            float4 v = make_float4(0.f, 0.f, 0.f, 0.f);
            if (p_am >= 0) v = *(const float4*)(xrow + k0 + kk);
            As[kk+0][am] = v.x; As[kk+1][am] = v.y;
            As[kk+2][am] = v.z; As[kk+3][am] = v.w;
        }
#pragma unroll
        for (int j = 0; j < 3; j++) {
            int c = bseg*4 + j*32;
            *(float4*)&Bs[bk][c] =
                *(const float4*)(Wb + (size_t)(k0 + bk) * HDIM + c);
        }
        __syncthreads();
#pragma unroll
        for (int kk = 0; kk < 32; kk++) {
            float a[4];
#pragma unroll
            for (int i = 0; i < 4; i++) a[i] = As[kk][ty*4 + i];
            float2 b0 = *(float2*)&Bs[kk][tx*6];
            float2 b1 = *(float2*)&Bs[kk][tx*6 + 2];
            float2 b2 = *(float2*)&Bs[kk][tx*6 + 4];
#pragma unroll
            for (int i = 0; i < 4; i++) {
                acc[i][0] += a[i]*b0.x; acc[i][1] += a[i]*b0.y;
                acc[i][2] += a[i]*b1.x; acc[i][3] += a[i]*b1.y;
                acc[i][4] += a[i]*b2.x; acc[i][5] += a[i]*b2.y;
            }
        }
        __syncthreads();
    }
#pragma unroll
    for (int i = 0; i < 4; i++) {
        int p = pidx[ty*4 + i];
        if (p < 0) continue;
        float* qp = g_q + (size_t)p * HDIM + tx*6;
#pragma unroll
        for (int j = 0; j < 6; j++) qp[j] = acc[i][j];
    }
}

/* ---------------- flash attention, shared KV across heads ---------------
 * Q and K stored TRANSPOSED in smem (Qt/Kt[d][row], pitch 64) so the QK
 * inner loop is two conflict-free LDS.128 per d; V row-major (pitch 98),
 * loads hoisted out of the 4-row loop.                                    */
__global__ void __launch_bounds__(256) attn_kernel() {
    extern __shared__ float sm[];
    const int VS = 98, PS = 65;
    float* Qt = sm;                    /* [96][64] */
    float* Kt = Qt + 96*64;            /* [96][64] */
    float* Vs = Kt + 96*64;            /* [64][98] */
    float* Ps = Vs + 64*VS;            /* [64][65] */
    float* row_m = Ps + 64*PS;
    float* row_l = row_m + 64;

    int b = blockIdx.z, h = blockIdx.y, q0 = blockIdx.x * 64;
    int tid = threadIdx.x;
    int tx = tid & 15, ty = tid >> 4;
    {
        int r = tid >> 2, d0 = (tid & 3) * 4;
        const float* qp = g_q + ((size_t)((b*NTOK + q0 + r)*NHEADS + h)) * HDIM;
#pragma unroll
        for (int j = 0; j < 6; j++) {
            int d = d0 + j*16;
            float4 v = *(const float4*)(qp + d);
            Qt[(d+0)*64 + r] = v.x; Qt[(d+1)*64 + r] = v.y;
            Qt[(d+2)*64 + r] = v.z; Qt[(d+3)*64 + r] = v.w;
        }
    }
    if (tid < 64) { row_m[tid] = -1e30f; row_l[tid] = 0.f; }
    float acc[4][6];
#pragma unroll
    for (int i = 0; i < 4; i++)
#pragma unroll
        for (int u = 0; u < 6; u++) acc[i][u] = 0.f;

    for (int jt = 0; jt < 16; jt++) {
        __syncthreads();
        {
            int r = tid >> 2, d0 = (tid & 3) * 4;
            int t = b*NTOK + jt*64 + r;
            const float* kp = g_k + (size_t)t * HDIM;
            const float* vp = g_v + (size_t)t * HDIM;
#pragma unroll
            for (int j = 0; j < 6; j++) {
                int d = d0 + j*16;
                float4 kv4 = *(const float4*)(kp + d);
                Kt[(d+0)*64 + r] = kv4.x; Kt[(d+1)*64 + r] = kv4.y;
                Kt[(d+2)*64 + r] = kv4.z; Kt[(d+3)*64 + r] = kv4.w;
                float4 vv4 = *(const float4*)(vp + d);
                Vs[r*VS + d] = vv4.x; Vs[r*VS + d+1] = vv4.y;
                Vs[r*VS + d+2] = vv4.z; Vs[r*VS + d+3] = vv4.w;
            }
        }
        __syncthreads();

        float s[4][4];
#pragma unroll
        for (int i = 0; i < 4; i++)
#pragma unroll
            for (int j = 0; j < 4; j++) s[i][j] = 0.f;
#pragma unroll 2
        for (int d = 0; d < HDIM; d++) {
            float4 a4 = *(float4*)&Qt[d*64 + ty*4];
            float4 k4 = *(float4*)&Kt[d*64 + tx*4];
            s[0][0] += a4.x*k4.x; s[0][1] += a4.x*k4.y; s[0][2] += a4.x*k4.z; s[0][3] += a4.x*k4.w;
            s[1][0] += a4.y*k4.x; s[1][1] += a4.y*k4.y; s[1][2] += a4.y*k4.z; s[1][3] += a4.y*k4.w;
            s[2][0] += a4.z*k4.x; s[2][1] += a4.z*k4.y; s[2][2] += a4.z*k4.z; s[2][3] += a4.z*k4.w;
            s[3][0] += a4.w*k4.x; s[3][1] += a4.w*k4.y; s[3][2] += a4.w*k4.z; s[3][3] += a4.w*k4.w;
        }

        float fac[4];
#pragma unroll
        for (int i = 0; i < 4; i++) {
            int r = ty*4 + i;
            float mo = row_m[r];   /* ordered vs tx==0 write below via shfl syncs */
            float tm = -1e30f;
#pragma unroll
            for (int j = 0; j < 4; j++) { s[i][j] *= ATTSCALE; tm = fmaxf(tm, s[i][j]); }
#pragma unroll
            for (int off = 8; off > 0; off >>= 1)
                tm = fmaxf(tm, __shfl_xor_sync(0xffffffffu, tm, off));
            float mn = fmaxf(mo, tm);
            float ls = 0.f;
#pragma unroll
            for (int j = 0; j < 4; j++) { float p = __expf(s[i][j] - mn); s[i][j] = p; ls += p; }
#pragma unroll
            for (int off = 8; off > 0; off >>= 1)
                ls += __shfl_xor_sync(0xffffffffu, ls, off);
            fac[i] = __expf(mo - mn);
            Ps[r*PS + tx*4 + 0] = s[i][0];
            Ps[r*PS + tx*4 + 1] = s[i][1];
            Ps[r*PS + tx*4 + 2] = s[i][2];
            Ps[r*PS + tx*4 + 3] = s[i][3];
            if (tx == 0) { row_m[r] = mn; row_l[r] = row_l[r]*fac[i] + ls; }
        }
        __syncthreads();
#pragma unroll
        for (int i = 0; i < 4; i++) {
            float f = fac[i];
#pragma unroll
            for (int u = 0; u < 6; u++) acc[i][u] *= f;
        }
        for (int c = 0; c < 64; c++) {
            const float* vr = Vs + c*VS + tx*6;
            float2 v0 = *(const float2*)(vr);
            float2 v1 = *(const float2*)(vr + 2);
            float2 v2 = *(const float2*)(vr + 4);
#pragma unroll
            for (int i = 0; i < 4; i++) {
                float pv = Ps[(ty*4 + i)*PS + c];
                acc[i][0] += pv*v0.x; acc[i][1] += pv*v0.y;
                acc[i][2] += pv*v1.x; acc[i][3] += pv*v1.y;
                acc[i][4] += pv*v2.x; acc[i][5] += pv*v2.y;
            }
        }
    }
    __syncthreads();   /* make lane-0 row_l writes visible */
#pragma unroll
    for (int i = 0; i < 4; i++) {
        int r = ty*4 + i;
        float inv = 1.f / row_l[r];
        float* op = g_o + ((size_t)((b*NTOK + q0 + r)*NHEADS + h)) * HDIM + tx*6;
#pragma unroll
        for (int u = 0; u < 6; u++) op[u] = acc[i][u] * inv;
    }
}

/* ---------------- MoE reduce: contrib rows = (g*o) @ W2[e] -------------- */
__global__ void __launch_bounds__(256) reduce_kernel(const float* __restrict__ W2) {
    if ((int)blockIdx.x >= g_nt6) return;
    int e = g_t6e[blockIdx.x], row0 = g_t6row[blockIdx.x];
    int off = g_offsets[e], rows = g_offsets[e+1] - off;
    int rcount = rows - row0; if (rcount > 32) rcount = 32;
    int c0 = blockIdx.y * 128;
    __shared__ float As[96][33];
    __shared__ float Bs[32][128];
    __shared__ int   pidx[32];
    int tid = threadIdx.x;
    if (tid < 32) pidx[tid] = (tid < rcount) ? g_perm[off + row0 + tid] : -1;
    __syncthreads();
    {
        int m = tid >> 3, dseg = tid & 7;
        int p = pidx[m];
        float g = (p >= 0) ? g_gates[p] : 0.f;
        const float* orow = (p >= 0) ? g_o + (size_t)p * HDIM : g_o;
#pragma unroll
        for (int j = 0; j < 3; j++) {
            int d = dseg*4 + j*32;
            float4 v = make_float4(0.f, 0.f, 0.f, 0.f);
            if (p >= 0) v = *(const float4*)(orow + d);
            As[d+0][m] = g*v.x; As[d+1][m] = g*v.y;
            As[d+2][m] = g*v.z; As[d+3][m] = g*v.w;
        }
    }
    int tx = tid & 15, ty = tid >> 4;
    /* output columns: c0 + tx*4 + j  and  c0 + 64 + tx*4 + j  (conflict-free) */
    float acc[2][8];
#pragma unroll
    for (int i = 0; i < 2; i++)
#pragma unroll
        for (int j = 0; j < 8; j++) acc[i][j] = 0.f;
    const float* Wb = W2 + (size_t)e * HDIM * DIMSZ + c0;
    for (int d0 = 0; d0 < HDIM; d0 += 32) {
        __syncthreads();
        {
            int dd = tid >> 3, cseg = tid & 7;
#pragma unroll
            for (int j = 0; j < 4; j++) {
                int c = cseg*4 + j*32;
                *(float4*)&Bs[dd][c] =
                    *(const float4*)(Wb + (size_t)(d0 + dd) * DIMSZ + c);
            }
        }
        __syncthreads();
#pragma unroll
        for (int kk = 0; kk < 32; kk++) {
            float a[2];
            a[0] = As[d0 + kk][ty*2 + 0];
            a[1] = As[d0 + kk][ty*2 + 1];
            float4 b0 = *(float4*)&Bs[kk][tx*4];
            float4 b1 = *(float4*)&Bs[kk][64 + tx*4];
#pragma unroll
            for (int i = 0; i < 2; i++) {
                acc[i][0] += a[i]*b0.x; acc[i][1] += a[i]*b0.y;
                acc[i][2] += a[i]*b0.z; acc[i][3] += a[i]*b0.w;
                acc[i][4] += a[i]*b1.x; acc[i][5] += a[i]*b1.y;
                acc[i][6] += a[i]*b1.z; acc[i][7] += a[i]*b1.w;
            }
        }
    }
#pragma unroll
    for (int i = 0; i < 2; i++) {
        int p = pidx[ty*2 + i];
        if (p < 0) continue;
        float* op = g_contrib + (size_t)p * DIMSZ + c0;
#pragma unroll
        for (int j = 0; j < 4; j++) op[tx*4 + j]      = acc[i][j];
#pragma unroll
        for (int j = 0; j < 4; j++) op[64 + tx*4 + j] = acc[i][4 + j];
    }
}

/* ---------------- combine over heads ------------------------------------ */
__global__ void combine_kernel(float* __restrict__ out) {
    size_t idx = (size_t)blockIdx.x * 256 + threadIdx.x;
    if (idx >= (size_t)TOK * DIMSZ) return;
    size_t t = idx / DIMSZ, c = idx % DIMSZ;
    float s = 0.f;
#pragma unroll
    for (int h = 0; h < NHEADS; h++)
        s += g_contrib[(t*NHEADS + h) * DIMSZ + c];
    out[idx] = s;
}

/* ---------------- aux loss ---------------------------------------------- */
__global__ void aux_kernel(float* __restrict__ out) {
    if (threadIdx.x != 0) return;
    float ms = 0.f;
    for (int e = 0; e < NEXP; e++) ms += g_me[e];
    float sw = 0.f;
    for (int e = 0; e < NEXP; e++)
        sw += (g_me[e] / ms) * ((float)g_counts[e] / (float)ROWS);
    sw *= (float)NEXP;
    float z = g_zsum / (float)TOK;
    out[(size_t)TOK * DIMSZ] = 0.1f * sw + 0.001f * z;
}

/* ---------------- launch ------------------------------------------------ */
extern "C" void kernel_launch(void* const* d_in, const int* in_sizes, int n_in,
                              void* d_out, int out_size) {
    const float* x    = (const float*)d_in[0];
    const float* Wg   = (const float*)d_in[1];
    const float* W1   = (const float*)d_in[2];
    const float* W2   = (const float*)d_in[3];
    const float* Wkv  = (const float*)d_in[4];
    const float* bkv  = (const float*)d_in[5];
    const int*   task = (const int*)  d_in[6];
    float* out = (float*)d_out;

    /* Qt + Kt + Vs + Ps + m/l */
    const int attn_smem = (96*64*2 + 64*98 + 64*65 + 128) * 4; /* 91008 B */
    cudaFuncSetAttribute(attn_kernel,
                         cudaFuncAttributeMaxDynamicSharedMemorySize, attn_smem);

    zero_kernel<<<1, 64>>>();
    gate_kernel<<<TOK, 192>>>(x, Wg, task);
    scan_kernel<<<1, 1>>>();
    scatter_kernel<<<ROWS/256, 256>>>();
    kv_kernel<<<dim3(TOK/64, 3), 256>>>(x, Wkv, bkv);
    map_kernel<<<1100, 256>>>(x, W1);
    attn_kernel<<<dim3(NTOK/64, NHEADS, BATCH), 256, attn_smem>>>();
    reduce_kernel<<<dim3(2200, 6), 256>>>(W2);
    combine_kernel<<<(TOK*DIMSZ + 255)/256, 256>>>(out);
    if (out_size > TOK*DIMSZ) aux_kernel<<<1, 32>>>(out);
}

// round 14
// speedup vs baseline: 2.0390x; 2.0390x over previous
#include <cuda_runtime.h>
#include <math.h>
#include <stdint.h>

#define BATCH   8
#define NTOK    1024
#define DIMSZ   768
#define NHEADS  8
#define HDIM    96
#define NEXP    24
#define TOK     (BATCH*NTOK)        /* 8192  */
#define ROWS    (TOK*NHEADS)        /* 65536 */
#define ATTSCALE 0.10206207261596577f  /* 96^-0.5 */

/* ---------------- scratch (static device memory; no allocations) -------- */
__device__ float g_k[TOK*HDIM];
__device__ float g_v[TOK*HDIM];
__device__ float g_q[(size_t)ROWS*HDIM];
__device__ float g_o[(size_t)ROWS*HDIM];
__device__ float g_contrib[(size_t)ROWS*DIMSZ];   /* 192 MB */
__device__ int   g_topi[ROWS];
__device__ float g_gates[ROWS];
__device__ int   g_perm[ROWS];
__device__ float g_me[NEXP];
__device__ int   g_counts[NEXP];
__device__ int   g_cursor[NEXP];
__device__ int   g_offsets[NEXP+1];
__device__ float g_zsum;
__device__ int   g_t4e[1100], g_t4row[1100], g_nt4;
__device__ int   g_t6e[2200], g_t6row[2200], g_nt6;

/* ---------------- tf32 helpers ------------------------------------------ */
__device__ __forceinline__ float to_tf32(float x) {
    uint32_t u;
    asm("cvt.rna.tf32.f32 %0, %1;" : "=r"(u) : "f"(x));
    return __uint_as_float(u);
}
__device__ __forceinline__ void mma8(float d[4], const uint32_t a[4], const uint32_t b[2]) {
    asm("mma.sync.aligned.m16n8k8.row.col.f32.tf32.tf32.f32 "
        "{%0,%1,%2,%3}, {%4,%5,%6,%7}, {%8,%9}, {%0,%1,%2,%3};"
        : "+f"(d[0]), "+f"(d[1]), "+f"(d[2]), "+f"(d[3])
        : "r"(a[0]), "r"(a[1]), "r"(a[2]), "r"(a[3]), "r"(b[0]), "r"(b[1]));
}

/* ---------------- zero counters ---------------------------------------- */
__global__ void zero_kernel() {
    int i = threadIdx.x;
    if (i < NEXP) { g_me[i] = 0.f; g_counts[i] = 0; g_cursor[i] = 0; }
    if (i == 63) g_zsum = 0.f;
}

/* ---------------- gating: logits, softmax, top-8, aux partials ---------- */
__global__ void gate_kernel(const float* __restrict__ x,
                            const float* __restrict__ Wg,
                            const int*   __restrict__ taskp) {
    int t = blockIdx.x;
    int tid = threadIdx.x;            /* 192 threads */
    __shared__ float xs[DIMSZ];
    __shared__ float lred[6][NEXP];
    __shared__ float logits[NEXP];
    __shared__ float probs[NEXP];

    for (int i = tid; i < DIMSZ; i += 192) xs[i] = x[(size_t)t*DIMSZ + i];
    __syncthreads();

    int task = *taskp;
    const float* W = Wg + (size_t)task * DIMSZ * NEXP;

    float acc[NEXP];
#pragma unroll
    for (int e = 0; e < NEXP; e++) acc[e] = 0.f;
    for (int d = tid; d < DIMSZ; d += 192) {
        float xv = xs[d];
        const float* row = W + (size_t)d * NEXP;
#pragma unroll
        for (int e = 0; e < NEXP; e++) acc[e] += xv * row[e];
    }
#pragma unroll
    for (int off = 16; off > 0; off >>= 1)
#pragma unroll
        for (int e = 0; e < NEXP; e++)
            acc[e] += __shfl_xor_sync(0xffffffffu, acc[e], off);
    int warp = tid >> 5, lane = tid & 31;
    if (lane == 0)
#pragma unroll
        for (int e = 0; e < NEXP; e++) lred[warp][e] = acc[e];
    __syncthreads();
    if (tid < NEXP) {
        float s = 0.f;
#pragma unroll
        for (int w = 0; w < 6; w++) s += lred[w][tid];
        logits[tid] = s;
    }
    __syncthreads();

    if (tid == 0) {
        float mx = -1e30f;
        for (int e = 0; e < NEXP; e++) mx = fmaxf(mx, logits[e]);
        float se = 0.f;
        for (int e = 0; e < NEXP; e++) se += expf(logits[e] - mx);
        float lse = mx + logf(se);
        atomicAdd(&g_zsum, lse * lse);
        float inv = 1.f / se;
        for (int e = 0; e < NEXP; e++) probs[e] = expf(logits[e] - mx) * inv;
        bool used[NEXP];
        for (int e = 0; e < NEXP; e++) used[e] = false;
        float gsum = 0.f; int idx[NHEADS]; float gv[NHEADS];
        for (int h = 0; h < NHEADS; h++) {
            float best = -1.f; int bi = 0;
            for (int e = 0; e < NEXP; e++)
                if (!used[e] && probs[e] > best) { best = probs[e]; bi = e; }
            used[bi] = true; idx[h] = bi; gv[h] = best; gsum += best;
        }
        float dn = 1.f / (gsum + 1e-6f);
        for (int h = 0; h < NHEADS; h++) {
            g_topi[t*NHEADS + h]  = idx[h];
            g_gates[t*NHEADS + h] = gv[h] * dn;
            atomicAdd(&g_counts[idx[h]], 1);
        }
    }
    __syncthreads();
    if (tid < NEXP) atomicAdd(&g_me[tid], probs[tid]);
}

/* ---------------- offsets + tile maps (single thread) ------------------- */
__global__ void scan_kernel() {
    int off = 0;
    for (int e = 0; e < NEXP; e++) { g_offsets[e] = off; off += g_counts[e]; }
    g_offsets[NEXP] = off;
    int n4 = 0, n6 = 0;
    for (int e = 0; e < NEXP; e++) {
        int r = g_counts[e];
        for (int i = 0; i < r; i += 64) { g_t4e[n4] = e; g_t4row[n4] = i; n4++; }
        for (int i = 0; i < r; i += 32) { g_t6e[n6] = e; g_t6row[n6] = i; n6++; }
    }
    g_nt4 = n4; g_nt6 = n6;
}

/* ---------------- scatter rows into per-expert lists -------------------- */
__global__ void scatter_kernel() {
    int i = blockIdx.x * 256 + threadIdx.x;
    if (i >= ROWS) return;
    int e = g_topi[i];
    int pos = g_offsets[e] + atomicAdd(&g_cursor[e], 1);
    g_perm[pos] = i;
}

/* ---------------- kv = x @ Wkv + b_kv ----------------------------------- */
__global__ void __launch_bounds__(256) kv_kernel(
                          const float* __restrict__ x,
                          const float* __restrict__ Wkv,
                          const float* __restrict__ bkv) {
    int bm = blockIdx.x * 64, bn = blockIdx.y * 64;
    __shared__ float As[16][65];
    __shared__ float Bs[16][64];
    int tid = threadIdx.x;
    int tx = tid & 15, ty = tid >> 4;
    float acc[4][4];
#pragma unroll
    for (int i = 0; i < 4; i++)
#pragma unroll
        for (int j = 0; j < 4; j++) acc[i][j] = 0.f;
    int lr = tid >> 2, lc4 = (tid & 3) * 4;
    int br = tid >> 4, bc4 = (tid & 15) * 4;
    for (int k0 = 0; k0 < DIMSZ; k0 += 16) {
        float4 av = *(const float4*)(x + (size_t)(bm + lr) * DIMSZ + k0 + lc4);
        As[lc4+0][lr] = av.x; As[lc4+1][lr] = av.y;
        As[lc4+2][lr] = av.z; As[lc4+3][lr] = av.w;
        *(float4*)&Bs[br][bc4] =
            *(const float4*)(Wkv + (size_t)(k0 + br) * 192 + bn + bc4);
        __syncthreads();
#pragma unroll
        for (int kk = 0; kk < 16; kk++) {
            float a[4];
#pragma unroll
            for (int i = 0; i < 4; i++) a[i] = As[kk][ty*4 + i];
            float4 b = *(float4*)&Bs[kk][tx*4];
#pragma unroll
            for (int i = 0; i < 4; i++) {
                acc[i][0] += a[i]*b.x; acc[i][1] += a[i]*b.y;
                acc[i][2] += a[i]*b.z; acc[i][3] += a[i]*b.w;
            }
        }
        __syncthreads();
    }
#pragma unroll
    for (int i = 0; i < 4; i++) {
        int t = bm + ty*4 + i;
#pragma unroll
        for (int j = 0; j < 4; j++) {
            int col = bn + tx*4 + j;
            float val = acc[i][j] + bkv[col];
            if (col < HDIM) g_k[(size_t)t*HDIM + col] = val;
            else            g_v[(size_t)t*HDIM + col - HDIM] = val;
        }
    }
}

/* ---------------- MoE map: tf32 mma gathered GEMM -----------------------
 * 64-row expert tile x 96 cols, K=768 staged 32 wide. 8 warps = 4 M-tiles
 * x 2 N-tiles; per warp m16 x n48. A-frag = Q pattern (AP=36 ≡ 4 mod 32),
 * B-frag = V pattern (BP=104 ≡ 8), C-store = O pattern.                   */
__global__ void __launch_bounds__(256) map_kernel(
                           const float* __restrict__ x,
                           const float* __restrict__ W1) {
    if ((int)blockIdx.x >= g_nt4) return;
    int e = g_t4e[blockIdx.x], row0 = g_t4row[blockIdx.x];
    int off = g_offsets[e], rows = g_offsets[e+1] - off;
    const int AP = 36, BP = 104;
    __shared__ float As[64*36];      /*  9216 B */
    __shared__ float Bs[32*104];     /* 13312 B */
    __shared__ int   pidx[64];
    int tid = threadIdx.x;
    int wid = tid >> 5, lane = tid & 31;
    int quad = lane >> 2, qt = lane & 3;
    int mt = wid & 3, nt = wid >> 2;

    if (tid < 64) {
        int r = row0 + tid;
        pidx[tid] = (r < rows) ? g_perm[off + r] : -1;
    }
    __syncthreads();

    int ar = tid >> 2, aseg = tid & 3;
    int p_ar = pidx[ar];
    const float* xrow = (p_ar >= 0) ? x + (size_t)(p_ar >> 3) * DIMSZ : x;
    int bd = tid >> 3, bseg = tid & 7;
    const float* Wb = W1 + (size_t)e * DIMSZ * HDIM;

    float facc[6][4];
#pragma unroll
    for (int nn = 0; nn < 6; nn++)
#pragma unroll
        for (int j = 0; j < 4; j++) facc[nn][j] = 0.f;

    for (int k0 = 0; k0 < DIMSZ; k0 += 32) {
        __syncthreads();
#pragma unroll
        for (int u = 0; u < 2; u++) {
            int c = aseg*4 + u*16;
            float4 v = make_float4(0.f, 0.f, 0.f, 0.f);
            if (p_ar >= 0) v = *(const float4*)(xrow + k0 + c);
            As[ar*AP + c + 0] = to_tf32(v.x);
            As[ar*AP + c + 1] = to_tf32(v.y);
            As[ar*AP + c + 2] = to_tf32(v.z);
            As[ar*AP + c + 3] = to_tf32(v.w);
        }
#pragma unroll
        for (int j = 0; j < 3; j++) {
            int c = bseg*4 + j*32;
            float4 w = *(const float4*)(Wb + (size_t)(k0 + bd) * HDIM + c);
            Bs[bd*BP + c + 0] = to_tf32(w.x);
            Bs[bd*BP + c + 1] = to_tf32(w.y);
            Bs[bd*BP + c + 2] = to_tf32(w.z);
            Bs[bd*BP + c + 3] = to_tf32(w.w);
        }
        __syncthreads();
#pragma unroll
        for (int kt = 0; kt < 4; kt++) {
            int kk = kt * 8;
            uint32_t a[4];
            a[0] = __float_as_uint(As[(mt*16+quad)*AP   + kk + qt]);
            a[1] = __float_as_uint(As[(mt*16+quad+8)*AP + kk + qt]);
            a[2] = __float_as_uint(As[(mt*16+quad)*AP   + kk + qt + 4]);
            a[3] = __float_as_uint(As[(mt*16+quad+8)*AP + kk + qt + 4]);
#pragma unroll
            for (int nn = 0; nn < 6; nn++) {
                uint32_t bb[2];
                bb[0] = __float_as_uint(Bs[(kk+qt)*BP   + nt*48 + nn*8 + quad]);
                bb[1] = __float_as_uint(Bs[(kk+qt+4)*BP + nt*48 + nn*8 + quad]);
                mma8(facc[nn], a, bb);
            }
        }
    }

    int p0 = pidx[mt*16 + quad], p1 = pidx[mt*16 + quad + 8];
#pragma unroll
    for (int nn = 0; nn < 6; nn++) {
        int c = nt*48 + nn*8 + 2*qt;
        if (p0 >= 0)
            *(float2*)(g_q + (size_t)p0 * HDIM + c) = make_float2(facc[nn][0], facc[nn][1]);
        if (p1 >= 0)
            *(float2*)(g_q + (size_t)p1 * HDIM + c) = make_float2(facc[nn][2], facc[nn][3]);
    }
}

/* ---------------- flash attention: tf32 mma.sync m16n8k8 ---------------- */
__global__ void __launch_bounds__(256) attn_kernel() {
    extern __shared__ float sm[];
    const int QP = 100, KP = 100, VP = 104, PP = 68;
    float* Qs = sm;                  /* [128][100] */
    float* Ks = Qs + 128*QP;         /* [64][100]  */
    float* Vs = Ks + 64*KP;          /* [64][104]  */
    float* Ps = Vs + 64*VP;          /* [128][68]  */

    int b = blockIdx.z, h = blockIdx.y, q0 = blockIdx.x * 128;
    int tid = threadIdx.x;
    int wid = tid >> 5, lane = tid & 31;
    int quad = lane >> 2, qt = lane & 3;
    int wrow = wid * 16;

    {
        int r = tid >> 1, d0 = (tid & 1) * 48;
        const float* qp = g_q + ((size_t)((b*NTOK + q0 + r)*NHEADS + h))*HDIM + d0;
        float* dst = Qs + r*QP + d0;
#pragma unroll
        for (int j = 0; j < 12; j++) {
            float4 v = *(const float4*)(qp + j*4);
            dst[j*4+0] = to_tf32(v.x * ATTSCALE);
            dst[j*4+1] = to_tf32(v.y * ATTSCALE);
            dst[j*4+2] = to_tf32(v.z * ATTSCALE);
            dst[j*4+3] = to_tf32(v.w * ATTSCALE);
        }
    }

    float m0 = -1e30f, m1 = -1e30f, l0 = 0.f, l1 = 0.f;
    float acc[12][4];
#pragma unroll
    for (int nn = 0; nn < 12; nn++)
#pragma unroll
        for (int j = 0; j < 4; j++) acc[nn][j] = 0.f;

    int pr0 = (wrow + quad) * PP, pr1 = (wrow + quad + 8) * PP;

    for (int jt = 0; jt < 16; jt++) {
        __syncthreads();
        {
            int r = tid >> 2, d0 = (tid & 3) * 4;
            int t = b*NTOK + jt*64 + r;
            const float* kp = g_k + (size_t)t * HDIM;
            const float* vp = g_v + (size_t)t * HDIM;
#pragma unroll
            for (int j = 0; j < 6; j++) {
                int d = d0 + j*16;
                float4 kv = *(const float4*)(kp + d);
                Ks[r*KP+d+0] = to_tf32(kv.x); Ks[r*KP+d+1] = to_tf32(kv.y);
                Ks[r*KP+d+2] = to_tf32(kv.z); Ks[r*KP+d+3] = to_tf32(kv.w);
                float4 vv = *(const float4*)(vp + d);
                Vs[r*VP+d+0] = to_tf32(vv.x); Vs[r*VP+d+1] = to_tf32(vv.y);
                Vs[r*VP+d+2] = to_tf32(vv.z); Vs[r*VP+d+3] = to_tf32(vv.w);
            }
        }
        __syncthreads();

        float s[8][4];
#pragma unroll
        for (int n = 0; n < 8; n++)
#pragma unroll
            for (int j = 0; j < 4; j++) s[n][j] = 0.f;
#pragma unroll
        for (int kt = 0; kt < 12; kt++) {
            int k0 = kt * 8;
            uint32_t a[4];
            a[0] = __float_as_uint(Qs[(wrow+quad)*QP   + k0 + qt]);
            a[1] = __float_as_uint(Qs[(wrow+quad+8)*QP + k0 + qt]);
            a[2] = __float_as_uint(Qs[(wrow+quad)*QP   + k0 + qt + 4]);
            a[3] = __float_as_uint(Qs[(wrow+quad+8)*QP + k0 + qt + 4]);
#pragma unroll
            for (int n = 0; n < 8; n++) {
                uint32_t bb[2];
                bb[0] = __float_as_uint(Ks[(n*8+quad)*KP + k0 + qt]);
                bb[1] = __float_as_uint(Ks[(n*8+quad)*KP + k0 + qt + 4]);
                mma8(s[n], a, bb);
            }
        }

        float tm0 = -1e30f, tm1 = -1e30f;
#pragma unroll
        for (int n = 0; n < 8; n++) {
            tm0 = fmaxf(tm0, fmaxf(s[n][0], s[n][1]));
            tm1 = fmaxf(tm1, fmaxf(s[n][2], s[n][3]));
        }
        tm0 = fmaxf(tm0, __shfl_xor_sync(0xffffffffu, tm0, 1));
        tm0 = fmaxf(tm0, __shfl_xor_sync(0xffffffffu, tm0, 2));
        tm1 = fmaxf(tm1, __shfl_xor_sync(0xffffffffu, tm1, 1));
        tm1 = fmaxf(tm1, __shfl_xor_sync(0xffffffffu, tm1, 2));
        float mn0 = fmaxf(m0, tm0), mn1 = fmaxf(m1, tm1);
        float fac0 = __expf(m0 - mn0), fac1 = __expf(m1 - mn1);
        float ls0 = 0.f, ls1 = 0.f;
#pragma unroll
        for (int n = 0; n < 8; n++) {
            float p0 = __expf(s[n][0] - mn0), p1 = __expf(s[n][1] - mn0);
            float p2 = __expf(s[n][2] - mn1), p3 = __expf(s[n][3] - mn1);
            ls0 += p0 + p1; ls1 += p2 + p3;
            int c = n*8 + 2*qt;
            Ps[pr0 + c] = to_tf32(p0); Ps[pr0 + c + 1] = to_tf32(p1);
            Ps[pr1 + c] = to_tf32(p2); Ps[pr1 + c + 1] = to_tf32(p3);
        }
        ls0 += __shfl_xor_sync(0xffffffffu, ls0, 1);
        ls0 += __shfl_xor_sync(0xffffffffu, ls0, 2);
        ls1 += __shfl_xor_sync(0xffffffffu, ls1, 1);
        ls1 += __shfl_xor_sync(0xffffffffu, ls1, 2);
        l0 = l0*fac0 + ls0; m0 = mn0;
        l1 = l1*fac1 + ls1; m1 = mn1;
#pragma unroll
        for (int nn = 0; nn < 12; nn++) {
            acc[nn][0] *= fac0; acc[nn][1] *= fac0;
            acc[nn][2] *= fac1; acc[nn][3] *= fac1;
        }
        __syncwarp();

#pragma unroll
        for (int kt = 0; kt < 8; kt++) {
            int k0 = kt * 8;
            uint32_t a[4];
            a[0] = __float_as_uint(Ps[pr0 + k0 + qt]);
            a[1] = __float_as_uint(Ps[pr1 + k0 + qt]);
            a[2] = __float_as_uint(Ps[pr0 + k0 + qt + 4]);
            a[3] = __float_as_uint(Ps[pr1 + k0 + qt + 4]);
#pragma unroll
            for (int nn = 0; nn < 12; nn++) {
                uint32_t bb[2];
                bb[0] = __float_as_uint(Vs[(k0+qt)*VP   + nn*8 + quad]);
                bb[1] = __float_as_uint(Vs[(k0+qt+4)*VP + nn*8 + quad]);
                mma8(acc[nn], a, bb);
            }
        }
    }

    float inv0 = 1.f / l0, inv1 = 1.f / l1;
    int rg = q0 + wrow + quad;
    float* o0 = g_o + ((size_t)((b*NTOK + rg)*NHEADS + h))*HDIM;
    float* o1 = g_o + ((size_t)((b*NTOK + rg + 8)*NHEADS + h))*HDIM;
#pragma unroll
    for (int nn = 0; nn < 12; nn++) {
        int c = nn*8 + 2*qt;
        *(float2*)(o0 + c) = make_float2(acc[nn][0]*inv0, acc[nn][1]*inv0);
        *(float2*)(o1 + c) = make_float2(acc[nn][2]*inv1, acc[nn][3]*inv1);
    }
}

/* ---------------- MoE reduce: tf32 mma, contrib = (g*o) @ W2[e] ---------
 * 32-row expert tile x 128-col chunk, K=96 staged 32 wide. 8 warps =
 * 2 M-tiles x 4 n32-tiles. A-frag = Q pattern (AP=100 ≡ 4 mod 32),
 * B-frag = V pattern (BP=136 ≡ 8), C-store = O pattern.                   */
__global__ void __launch_bounds__(256) reduce_kernel(const float* __restrict__ W2) {
    if ((int)blockIdx.x >= g_nt6) return;
    int e = g_t6e[blockIdx.x], row0 = g_t6row[blockIdx.x];
    int off = g_offsets[e], rows = g_offsets[e+1] - off;
    int c0 = blockIdx.y * 128;
    const int AP = 100, BP = 136;
    __shared__ float As[32*100];   /* 12800 B */
    __shared__ float Bs[32*136];   /* 17408 B */
    __shared__ int   pidx[32];
    int tid = threadIdx.x;
    int wid = tid >> 5, lane = tid & 31;
    int quad = lane >> 2, qt = lane & 3;
    int mt = wid & 1, nt = wid >> 1;   /* M-tile 0..1, N-tile 0..3 */

    if (tid < 32) {
        int r = row0 + tid;
        pidx[tid] = (r < rows) ? g_perm[off + r] : -1;
    }
    __syncthreads();

    {   /* A load: 32 rows x 96, gate-scaled, tf32 */
        int m = tid >> 3, seg = tid & 7;
        int p = pidx[m];
        float g = (p >= 0) ? g_gates[p] : 0.f;
        const float* orow = (p >= 0) ? g_o + (size_t)p * HDIM : g_o;
#pragma unroll
        for (int j = 0; j < 3; j++) {
            int d = seg*12 + j*4;
            float4 v = make_float4(0.f, 0.f, 0.f, 0.f);
            if (p >= 0) v = *(const float4*)(orow + d);
            As[m*AP + d+0] = to_tf32(g*v.x);
            As[m*AP + d+1] = to_tf32(g*v.y);
            As[m*AP + d+2] = to_tf32(g*v.z);
            As[m*AP + d+3] = to_tf32(g*v.w);
        }
    }

    float facc[4][4];
#pragma unroll
    for (int nn = 0; nn < 4; nn++)
#pragma unroll
        for (int j = 0; j < 4; j++) facc[nn][j] = 0.f;

    const float* Wb = W2 + (size_t)e * HDIM * DIMSZ + c0;
    for (int k0 = 0; k0 < HDIM; k0 += 32) {
        __syncthreads();
        {   /* B chunk load: 32 k-rows x 128 cols, tf32 */
            int dd = tid >> 3, cseg = tid & 7;
#pragma unroll
            for (int j = 0; j < 4; j++) {
                int c = cseg*4 + j*32;
                float4 w = *(const float4*)(Wb + (size_t)(k0 + dd) * DIMSZ + c);
                Bs[dd*BP + c + 0] = to_tf32(w.x);
                Bs[dd*BP + c + 1] = to_tf32(w.y);
                Bs[dd*BP + c + 2] = to_tf32(w.z);
                Bs[dd*BP + c + 3] = to_tf32(w.w);
            }
        }
        __syncthreads();
#pragma unroll
        for (int kt = 0; kt < 4; kt++) {
            int kk = kt * 8;
            uint32_t a[4];
            a[0] = __float_as_uint(As[(mt*16+quad)*AP   + k0 + kk + qt]);
            a[1] = __float_as_uint(As[(mt*16+quad+8)*AP + k0 + kk + qt]);
            a[2] = __float_as_uint(As[(mt*16+quad)*AP   + k0 + kk + qt + 4]);
            a[3] = __float_as_uint(As[(mt*16+quad+8)*AP + k0 + kk + qt + 4]);
#pragma unroll
            for (int nn = 0; nn < 4; nn++) {
                uint32_t bb[2];
                bb[0] = __float_as_uint(Bs[(kk+qt)*BP   + nt*32 + nn*8 + quad]);
                bb[1] = __float_as_uint(Bs[(kk+qt+4)*BP + nt*32 + nn*8 + quad]);
                mma8(facc[nn], a, bb);
            }
        }
    }

    int p0 = pidx[mt*16 + quad], p1 = pidx[mt*16 + quad + 8];
#pragma unroll
    for (int nn = 0; nn < 4; nn++) {
        int c = nt*32 + nn*8 + 2*qt;
        if (p0 >= 0)
            *(float2*)(g_contrib + (size_t)p0 * DIMSZ + c0 + c) =
                make_float2(facc[nn][0], facc[nn][1]);
        if (p1 >= 0)
            *(float2*)(g_contrib + (size_t)p1 * DIMSZ + c0 + c) =
                make_float2(facc[nn][2], facc[nn][3]);
    }
}

/* ---------------- combine over heads ------------------------------------ */
__global__ void combine_kernel(float* __restrict__ out) {
    size_t idx = (size_t)blockIdx.x * 256 + threadIdx.x;
    if (idx >= (size_t)TOK * DIMSZ) return;
    size_t t = idx / DIMSZ, c = idx % DIMSZ;
    float s = 0.f;
#pragma unroll
    for (int h = 0; h < NHEADS; h++)
        s += g_contrib[(t*NHEADS + h) * DIMSZ + c];
    out[idx] = s;
}

/* ---------------- aux loss ---------------------------------------------- */
__global__ void aux_kernel(float* __restrict__ out) {
    if (threadIdx.x != 0) return;
    float ms = 0.f;
    for (int e = 0; e < NEXP; e++) ms += g_me[e];
    float sw = 0.f;
    for (int e = 0; e < NEXP; e++)
        sw += (g_me[e] / ms) * ((float)g_counts[e] / (float)ROWS);
    sw *= (float)NEXP;
    float z = g_zsum / (float)TOK;
    out[(size_t)TOK * DIMSZ] = 0.1f * sw + 0.001f * z;
}

/* ---------------- launch ------------------------------------------------ */
extern "C" void kernel_launch(void* const* d_in, const int* in_sizes, int n_in,
                              void* d_out, int out_size) {
    const float* x    = (const float*)d_in[0];
    const float* Wg   = (const float*)d_in[1];
    const float* W1   = (const float*)d_in[2];
    const float* W2   = (const float*)d_in[3];
    const float* Wkv  = (const float*)d_in[4];
    const float* bkv  = (const float*)d_in[5];
    const int*   task = (const int*)  d_in[6];
    float* out = (float*)d_out;

    const int attn_smem = 34560 * 4;   /* 138240 B */
    cudaFuncSetAttribute(attn_kernel,
                         cudaFuncAttributeMaxDynamicSharedMemorySize, attn_smem);

    zero_kernel<<<1, 64>>>();
    gate_kernel<<<TOK, 192>>>(x, Wg, task);
    scan_kernel<<<1, 1>>>();
    scatter_kernel<<<ROWS/256, 256>>>();
    kv_kernel<<<dim3(TOK/64, 3), 256>>>(x, Wkv, bkv);
    map_kernel<<<1100, 256>>>(x, W1);
    attn_kernel<<<dim3(NTOK/128, NHEADS, BATCH), 256, attn_smem>>>();
    reduce_kernel<<<dim3(2200, 6), 256>>>(W2);
    combine_kernel<<<(TOK*DIMSZ + 255)/256, 256>>>(out);
    if (out_size > TOK*DIMSZ) aux_kernel<<<1, 32>>>(out);
}